// round 11
// baseline (speedup 1.0000x reference)
#include <cuda_runtime.h>
#include <cuda_bf16.h>

// Problem constants (fixed by reference setup_inputs)
#define BATCH 2
#define C_    256
#define H_    200
#define W_    272
#define HW_   (H_*W_)
#define NROI  256
#define PH    15
#define PW    15
#define SXG   30
#define SYG   30
#define OH    14
#define OW    14
#define SCALE_ 0.25f

#define FULLMASK 0xFFFFFFFFu
#define MAXENT 64

struct XEnt { int jlo; int jhi; float w0; float w1; };   // relative to x0e
struct alignas(16) Ent { int ro; float wA; float wB; int emit; };

__device__ XEnt g_x[NROI][32];
__device__ Ent  g_ent[NROI][MAXENT];
__device__ int  g_ne[NROI];
__device__ int4 g_hdr[NROI];   // {x0e, nw2, boff, span2-1}

// ---------------- Kernel A: per-roi tables + row-event stream ----------------
__global__ void roi_tab_kernel(const float* __restrict__ rois) {
    __shared__ int   s_rlo[SYG], s_rhi[SYG];
    __shared__ float s_w0[SYG], s_w1[SYG];

    int n = blockIdx.x;
    int t = threadIdx.x;   // 64 threads

    float x1 = rois[n*5+1] * SCALE_;
    float y1 = rois[n*5+2] * SCALE_;
    float x2 = rois[n*5+3] * SCALE_;
    float y2 = rois[n*5+4] * SCALE_;
    float cx = 0.5f*(x1+x2), cy = 0.5f*(y1+y2);
    float hw = 0.5f*(x2-x1), hh = 0.5f*(y2-y1);
    x1 = cx - hw; x2 = cx + hw;
    y1 = cy - hh; y2 = cy + hh;
    float roi_w = fmaxf(x2 - x1, 1.0f);
    float roi_h = fmaxf(y2 - y1, 1.0f);
    float bw = roi_w / (float)PW;
    float bh = roi_h / (float)PH;

    if (t < 32) {
        int i = t;
        float sx = x1 + ((float)i + 0.5f) * (bw * 0.5f);
        bool valid = (sx > -1.0f) && (sx < (float)W_);
        float c = fminf(fmaxf(sx, 0.0f), (float)(W_-1));
        float lo = floorf(c);
        int ilo = (int)lo;
        int ihi = min(ilo + 1, W_-1);
        float fr = c - lo;
        float v = valid ? 1.0f : 0.0f;

        int x0e = __shfl_sync(FULLMASK, ilo, 0) & ~1;   // even-aligned span start
        int jhi29 = __shfl_sync(FULLMASK, ihi, 29) - x0e;

        XEnt e;
        if (i < SXG) { e.jlo = ilo - x0e; e.jhi = ihi - x0e; e.w0 = v*(1.0f-fr); e.w1 = v*fr; }
        else         { e.jlo = 0; e.jhi = 0; e.w0 = 0.0f; e.w1 = 0.0f; }
        g_x[n][i] = e;

        if (i == 0) {
            int span2 = (jhi29 >> 1) + 1;          // float2 words needed
            int nw2 = ((span2 - 1) >> 5) + 1;
            nw2 = max(1, min(nw2, 2));
            int boff = (int)rois[n*5+0] * (C_ * HW_);
            g_hdr[n] = make_int4(x0e, nw2, boff, span2 - 1);
        }
    } else {
        int iy = t - 32;
        if (iy < SYG) {
            float sy = y1 + ((float)iy + 0.5f) * (bh * 0.5f);
            bool valid = (sy > -1.0f) && (sy < (float)H_);
            float c = fminf(fmaxf(sy, 0.0f), (float)(H_-1));
            float lo = floorf(c);
            int ilo = (int)lo;
            int ihi = min(ilo + 1, H_-1);
            float fr = c - lo;
            float v = valid ? 1.0f : 0.0f;
            s_rlo[iy] = ilo * W_;
            s_rhi[iy] = ihi * W_;
            s_w0[iy] = v*(1.0f-fr);
            s_w1[iy] = v*fr;
        }
    }
    __syncthreads();

    if (t == 63) {
        // Serial build of the row-event stream.
        int ne = 0;
        int capR[4]; int ncap = 0;   // rows of current k already accumulated (via prev wB)

        for (int k = 0; k < 15; k++) {
            // distinct nonzero rows of k
            int rr[4]; float ww[4]; int m = 0;
            for (int j = 2*k; j <= 2*k+1; j++) {
                int ra = s_rlo[j]; float wa = s_w0[j];
                int rb = s_rhi[j]; float wb = s_w1[j];
                if (wa != 0.0f) {
                    bool f = false;
                    for (int q = 0; q < m; q++) if (rr[q] == ra) { ww[q] += wa; f = true; break; }
                    if (!f) { rr[m] = ra; ww[m] = wa; m++; }
                }
                if (wb != 0.0f) {
                    bool f = false;
                    for (int q = 0; q < m; q++) if (rr[q] == rb) { ww[q] += wb; f = true; break; }
                    if (!f) { rr[m] = rb; ww[m] = wb; m++; }
                }
            }
            // distinct nonzero rows of k+1
            int rr2[4]; float ww2[4]; int m2 = 0;
            if (k < 14) {
                for (int j = 2*k+2; j <= 2*k+3; j++) {
                    int ra = s_rlo[j]; float wa = s_w0[j];
                    int rb = s_rhi[j]; float wb = s_w1[j];
                    if (wa != 0.0f) {
                        bool f = false;
                        for (int q = 0; q < m2; q++) if (rr2[q] == ra) { ww2[q] += wa; f = true; break; }
                        if (!f) { rr2[m2] = ra; ww2[m2] = wa; m2++; }
                    }
                    if (wb != 0.0f) {
                        bool f = false;
                        for (int q = 0; q < m2; q++) if (rr2[q] == rb) { ww2[q] += wb; f = true; break; }
                        if (!f) { rr2[m2] = rb; ww2[m2] = wb; m2++; }
                    }
                }
            }

            // count new rows (not already captured)
            int newCount = 0;
            for (int i = 0; i < m; i++) {
                bool inCap = false;
                for (int q = 0; q < ncap; q++) if (capR[q] == rr[i]) { inCap = true; break; }
                if (!inCap) newCount++;
            }

            int capR2[4]; int ncap2 = 0;
            if (newCount == 0) {
                // PA already complete; emit + prefetch one row of k+1
                Ent e;
                if (m2 > 0) { e.ro = rr2[0]; e.wB = ww2[0]; capR2[ncap2++] = rr2[0]; }
                else { e.ro = (m > 0) ? rr[0] : 0; e.wB = 0.0f; }
                e.wA = 0.0f; e.emit = 1;
                g_ent[n][ne++] = e;
            } else {
                int done = 0;
                for (int i = 0; i < m; i++) {
                    bool inCap = false;
                    for (int q = 0; q < ncap; q++) if (capR[q] == rr[i]) { inCap = true; break; }
                    if (inCap) continue;
                    Ent e;
                    e.ro = rr[i]; e.wA = ww[i]; e.wB = 0.0f;
                    for (int q = 0; q < m2; q++) if (rr2[q] == rr[i]) { e.wB = ww2[q]; capR2[ncap2++] = rr[i]; break; }
                    done++;
                    e.emit = (done == newCount) ? 1 : 0;
                    g_ent[n][ne++] = e;
                }
            }
            ncap = ncap2;
            for (int q = 0; q < ncap2; q++) capR[q] = capR2[q];
        }
        g_ne[n] = ne;
    }
}

// ---------------- Kernel B ----------------

// Horizontal gather of the two x-taps from the accumulated sum.
template<int NW2>
__device__ __forceinline__ float gath(float2 P0, float2 P1,
                                      int le, int lo_, int ew, int ow,
                                      int c0, int c1, float wx0, float wx1)
{
    float ex, oy;
    if (NW2 == 1) {
        ex = __shfl_sync(FULLMASK, P0.x, le);
        oy = __shfl_sync(FULLMASK, P0.y, lo_);
    } else {
        float a0 = __shfl_sync(FULLMASK, P0.x, le);
        float a1 = __shfl_sync(FULLMASK, P1.x, le);
        ex = ew ? a1 : a0;
        float b0 = __shfl_sync(FULLMASK, P0.y, lo_);
        float b1 = __shfl_sync(FULLMASK, P1.y, lo_);
        oy = ow ? b1 : b0;
    }
    float g0 = c0 ? oy : ex;
    float g1 = c1 ? oy : ex;
    return wx0*g0 + wx1*g1;
}

template<int NW2>
__device__ __forceinline__ void pair_proc(
    const float* __restrict__ pu, const float* __restrict__ pv,
    const int4* __restrict__ sent, int nE,
    int lane, int xs2, int c0, int c1, int le, int lo_, int ew, int ow,
    float wx0, float wx1,
    float* __restrict__ ou, float* __restrict__ ov)
{
    bool emitLane = ((lane & 1) == 0) && (lane < 28);
    int lofs = lane >> 1;

    int j0 = min(lane, xs2);
    int j1 = min(lane + 32, xs2);

    float2 z = make_float2(0.f, 0.f);
    float2 PAu0=z, PAu1=z, PAv0=z, PAv1=z;
    float2 PBu0=z, PBu1=z, PBv0=z, PBv1=z;
    float sPu = 0.0f, sPv = 0.0f;
    int kOut = 0;

    #pragma unroll 2
    for (int e = 0; e < nE; e++) {
        int4 en = sent[e];
        int ro = en.x;
        float wA = __int_as_float(en.y);
        float wB = __int_as_float(en.z);

        const float2* qu = (const float2*)(pu + ro);
        const float2* qv = (const float2*)(pv + ro);
        float2 a0 = __ldg(qu + j0);
        float2 b0 = __ldg(qv + j0);
        float2 a1, b1;
        if (NW2 > 1) { a1 = __ldg(qu + j1); b1 = __ldg(qv + j1); }

        PAu0.x += wA*a0.x;  PAu0.y += wA*a0.y;
        PBu0.x += wB*a0.x;  PBu0.y += wB*a0.y;
        PAv0.x += wA*b0.x;  PAv0.y += wA*b0.y;
        PBv0.x += wB*b0.x;  PBv0.y += wB*b0.y;
        if (NW2 > 1) {
            PAu1.x += wA*a1.x;  PAu1.y += wA*a1.y;
            PBu1.x += wB*a1.x;  PBu1.y += wB*a1.y;
            PAv1.x += wA*b1.x;  PAv1.y += wA*b1.y;
            PBv1.x += wB*b1.x;  PBv1.y += wB*b1.y;
        }

        if (en.w) {   // emit: current k complete
            float su = gath<NW2>(PAu0, PAu1, le, lo_, ew, ow, c0, c1, wx0, wx1);
            float sv = gath<NW2>(PAv0, PAv1, le, lo_, ew, ow, c0, c1, wx0, wx1);
            if (kOut) {
                float eu = sPu + su;
                float ev = sPv + sv;
                float tu = eu + __shfl_down_sync(FULLMASK, eu, 1);
                tu += __shfl_down_sync(FULLMASK, tu, 2);
                float tv = ev + __shfl_down_sync(FULLMASK, ev, 1);
                tv += __shfl_down_sync(FULLMASK, tv, 2);
                if (emitLane) {
                    int idx = (kOut - 1) * OW + lofs;
                    ou[idx] = tu * (1.0f/16.0f);
                    ov[idx] = tv * (1.0f/16.0f);
                }
            }
            sPu = su; sPv = sv;
            PAu0 = PBu0; PAv0 = PBv0; PBu0 = z; PBv0 = z;
            if (NW2 > 1) { PAu1 = PBu1; PAv1 = PBv1; PBu1 = z; PBv1 = z; }
            kOut++;
        }
    }
}

__global__ __launch_bounds__(256, 5)
void roi_align_kernel(const float* __restrict__ feat, float* __restrict__ out) {
    __shared__ int4 sent[MAXENT];

    int n  = blockIdx.x;
    int cg = blockIdx.y;
    int tid = threadIdx.x;
    int wid = tid >> 5, lane = tid & 31;

    if (tid < MAXENT) {
        sent[tid] = ((const int4*)g_ent[n])[tid];
    }
    __syncthreads();

    int nE = g_ne[n];
    int4 hdr = g_hdr[n];
    int x0e = hdr.x, nw2 = hdr.y, boff = hdr.z, xs2 = hdr.w;

    XEnt xe = g_x[n][lane];
    int c0 = xe.jlo & 1;
    int c1 = xe.jhi & 1;
    int je = c0 ? xe.jhi : xe.jlo;   // the even-column tap
    int jo = c0 ? xe.jlo : xe.jhi;   // the odd-column tap
    int le = (je >> 1) & 31, ew = je >> 6;
    int lo_ = (jo >> 1) & 31, ow = jo >> 6;
    float wx0 = xe.w0, wx1 = xe.w1;

    const float* base = feat + boff + x0e;
    int cbase = cg * 32 + wid * 4;

    #pragma unroll
    for (int p = 0; p < 2; p++) {
        int c = cbase + 2 * p;
        const float* pu = base + c * HW_;
        const float* pv = pu + HW_;
        float* ou = out + (size_t)(n * C_ + c) * (OH * OW);
        float* ov = ou + OH * OW;

        if (nw2 == 1)
            pair_proc<1>(pu, pv, sent, nE, lane, xs2, c0, c1, le, lo_, ew, ow, wx0, wx1, ou, ov);
        else
            pair_proc<2>(pu, pv, sent, nE, lane, xs2, c0, c1, le, lo_, ew, ow, wx0, wx1, ou, ov);
    }
}

extern "C" void kernel_launch(void* const* d_in, const int* in_sizes, int n_in,
                              void* d_out, int out_size) {
    const float* feat = (const float*)d_in[0];
    const float* rois = (const float*)d_in[1];
    float* out = (float*)d_out;

    roi_tab_kernel<<<NROI, 64>>>(rois);
    dim3 grid(NROI, 8);
    roi_align_kernel<<<grid, 256>>>(feat, out);
}

// round 12
// speedup vs baseline: 1.5189x; 1.5189x over previous
#include <cuda_runtime.h>
#include <cuda_bf16.h>

// Problem constants (fixed by reference setup_inputs)
#define BATCH 2
#define C_    256
#define H_    200
#define W_    272
#define HW_   (H_*W_)
#define NROI  256
#define PH    15
#define PW    15
#define SXG   30
#define SYG   30
#define OH    14
#define OW    14
#define SCALE_ 0.25f

#define FULLMASK 0xFFFFFFFFu

struct XEnt { int jlo; int jhi; float w0; float w1; };       // relative to x0e
struct alignas(16) RW { int r[4]; float w[4]; };             // folded distinct rows per k

__device__ XEnt g_x[NROI][32];
__device__ RW   g_rw[NROI][PH];
__device__ int4 g_hdr[NROI];       // {x0e, nw2, boff, span2-1}
__device__ int  g_rows[NROI];      // max distinct rows over k (2..4)
__device__ int  g_perm[NROI];      // cost-descending roi order

// ---------------- Kernel A: per-roi tables ----------------
__global__ void roi_tab_kernel(const float* __restrict__ rois) {
    int n = blockIdx.x;
    int t = threadIdx.x;   // 64 threads

    float x1 = rois[n*5+1] * SCALE_;
    float y1 = rois[n*5+2] * SCALE_;
    float x2 = rois[n*5+3] * SCALE_;
    float y2 = rois[n*5+4] * SCALE_;
    float cx = 0.5f*(x1+x2), cy = 0.5f*(y1+y2);
    float hw = 0.5f*(x2-x1), hh = 0.5f*(y2-y1);
    x1 = cx - hw; x2 = cx + hw;
    y1 = cy - hh; y2 = cy + hh;
    float roi_w = fmaxf(x2 - x1, 1.0f);
    float roi_h = fmaxf(y2 - y1, 1.0f);
    float bw = roi_w / (float)PW;
    float bh = roi_h / (float)PH;

    if (t < 32) {
        int i = t;
        float sx = x1 + ((float)i + 0.5f) * (bw * 0.5f);
        bool valid = (sx > -1.0f) && (sx < (float)W_);
        float c = fminf(fmaxf(sx, 0.0f), (float)(W_-1));
        float lo = floorf(c);
        int ilo = (int)lo;
        int ihi = min(ilo + 1, W_-1);
        float fr = c - lo;
        float v = valid ? 1.0f : 0.0f;

        int x0e = __shfl_sync(FULLMASK, ilo, 0) & ~1;   // even-aligned span start
        int jhi29 = __shfl_sync(FULLMASK, ihi, 29) - x0e;

        XEnt e;
        if (i < SXG) { e.jlo = ilo - x0e; e.jhi = ihi - x0e; e.w0 = v*(1.0f-fr); e.w1 = v*fr; }
        else         { e.jlo = 0; e.jhi = 0; e.w0 = 0.0f; e.w1 = 0.0f; }
        g_x[n][i] = e;

        if (i == 0) {
            int span2 = (jhi29 >> 1) + 1;          // float2 words needed
            int nw2 = ((span2 - 1) >> 5) + 1;      // 1 or 2 warp-words
            nw2 = max(1, min(nw2, 2));
            int boff = (int)rois[n*5+0] * (C_ * HW_);
            g_hdr[n] = make_int4(x0e, nw2, boff, span2 - 1);
        }
    } else if (t < 48) {
        int k = t - 32;
        int cnt = 2;
        if (k < PH) {
            int rr[4]; float ww[4]; int m = 0;

            #pragma unroll
            for (int j = 0; j < 2; j++) {
                int iy = 2*k + j;
                float sy = y1 + ((float)iy + 0.5f) * (bh * 0.5f);
                bool valid = (sy > -1.0f) && (sy < (float)H_);
                float c = fminf(fmaxf(sy, 0.0f), (float)(H_-1));
                float lo = floorf(c);
                int ilo = (int)lo;
                int ihi = min(ilo + 1, H_-1);
                float fr = c - lo;
                float v = valid ? 1.0f : 0.0f;
                float w0 = v*(1.0f-fr), w1 = v*fr;
                int r0 = ilo * W_, r1 = ihi * W_;

                if (w0 != 0.0f) {
                    bool done = false;
                    for (int q = 0; q < m; q++) if (rr[q] == r0) { ww[q] += w0; done = true; break; }
                    if (!done) { rr[m] = r0; ww[m] = w0; m++; }
                }
                if (w1 != 0.0f) {
                    bool done = false;
                    for (int q = 0; q < m; q++) if (rr[q] == r1) { ww[q] += w1; done = true; break; }
                    if (!done) { rr[m] = r1; ww[m] = w1; m++; }
                }
            }
            if (m == 0) { rr[0] = 0; ww[0] = 0.0f; m = 1; }
            cnt = max(m, 2);
            for (int q = m; q < 4; q++) { rr[q] = rr[0]; ww[q] = 0.0f; }

            RW rw;
            #pragma unroll
            for (int q = 0; q < 4; q++) { rw.r[q] = rr[q]; rw.w[q] = ww[q]; }
            g_rw[n][k] = rw;
        }
        // max over the 16 lanes of this group (lane ids 0..15 of warp 1)
        int mx = cnt;
        #pragma unroll
        for (int d = 8; d >= 1; d >>= 1)
            mx = max(mx, __shfl_xor_sync(0xFFFFu, mx, d));
        if (k == 0) g_rows[n] = mx;
    }
}

// ---------------- Kernel A2: cost-descending bitonic sort of rois ----------------
__global__ void roi_sort_kernel() {
    __shared__ unsigned skey[NROI];
    int t = threadIdx.x;

    int4 hdr = g_hdr[t];
    int cost = g_rows[t] * hdr.y;                 // 2..8
    // key: cost (hi) | span (mid) | idx (lo 8 bits)
    unsigned key = ((unsigned)cost << 20) | (((unsigned)hdr.w & 0xFFF) << 8) | (unsigned)t;
    skey[t] = key;
    __syncthreads();

    for (int k = 2; k <= NROI; k <<= 1) {
        for (int j = k >> 1; j > 0; j >>= 1) {
            int ixj = t ^ j;
            if (ixj > t) {
                unsigned a = skey[t], b = skey[ixj];
                bool seg = ((t & k) == 0);
                // descending sort: in 'seg' segments keep larger first
                if (seg ? (a < b) : (a > b)) { skey[t] = b; skey[ixj] = a; }
            }
            __syncthreads();
        }
    }
    g_perm[t] = (int)(skey[t] & 0xFFu);
}

// ---------------- Kernel B ----------------

// Horizontal gather of the two x-taps from the accumulated pair-sum.
template<int NW2>
__device__ __forceinline__ float gath(float2 P0, float2 P1,
                                      int le, int lo_, int ew, int ow,
                                      int c0, int c1, float wx0, float wx1)
{
    float ex, oy;
    if (NW2 == 1) {
        ex = __shfl_sync(FULLMASK, P0.x, le);
        oy = __shfl_sync(FULLMASK, P0.y, lo_);
    } else {
        float a0 = __shfl_sync(FULLMASK, P0.x, le);
        float a1 = __shfl_sync(FULLMASK, P1.x, le);
        ex = ew ? a1 : a0;
        float b0 = __shfl_sync(FULLMASK, P0.y, lo_);
        float b1 = __shfl_sync(FULLMASK, P1.y, lo_);
        oy = ow ? b1 : b0;
    }
    float g0 = c0 ? oy : ex;
    float g1 = c1 ? oy : ex;
    return wx0*g0 + wx1*g1;
}

template<int NW2, int ROWS>
__device__ __forceinline__ void pair_proc(
    const float* __restrict__ pu, const float* __restrict__ pv,
    const RW* __restrict__ srw,
    int lane, int xs2, int c0, int c1, int le, int lo_, int ew, int ow,
    float wx0, float wx1,
    float* __restrict__ ou, float* __restrict__ ov)
{
    bool emit = ((lane & 1) == 0) && (lane < 28);
    int lofs = lane >> 1;

    int j0 = min(lane, xs2);
    int j1 = min(lane + 32, xs2);   // collapses onto last needed line

    float sPu = 0.0f, sPv = 0.0f;

    #pragma unroll 3
    for (int k = 0; k < 15; k++) {
        RW rw = srw[k];
        float2 Pu0 = make_float2(0.f,0.f), Pu1 = make_float2(0.f,0.f);
        float2 Pv0 = make_float2(0.f,0.f), Pv1 = make_float2(0.f,0.f);

        float2 au[ROWS], bu[ROWS], a1u[ROWS], b1u[ROWS];
        #pragma unroll
        for (int q = 0; q < ROWS; q++) {
            const float2* qu = (const float2*)(pu + rw.r[q]);
            const float2* qv = (const float2*)(pv + rw.r[q]);
            au[q] = __ldg(qu + j0);
            bu[q] = __ldg(qv + j0);
            if (NW2 > 1) {
                a1u[q] = __ldg(qu + j1);
                b1u[q] = __ldg(qv + j1);
            }
        }
        #pragma unroll
        for (int q = 0; q < ROWS; q++) {
            float w = rw.w[q];
            Pu0.x += w * au[q].x;  Pu0.y += w * au[q].y;
            Pv0.x += w * bu[q].x;  Pv0.y += w * bu[q].y;
            if (NW2 > 1) {
                Pu1.x += w * a1u[q].x;  Pu1.y += w * a1u[q].y;
                Pv1.x += w * b1u[q].x;  Pv1.y += w * b1u[q].y;
            }
        }

        float su = gath<NW2>(Pu0, Pu1, le, lo_, ew, ow, c0, c1, wx0, wx1);
        float sv = gath<NW2>(Pv0, Pv1, le, lo_, ew, ow, c0, c1, wx0, wx1);

        if (k) {
            float eu = sPu + su;
            float ev = sPv + sv;
            float tu = eu + __shfl_down_sync(FULLMASK, eu, 1);
            tu += __shfl_down_sync(FULLMASK, tu, 2);
            float tv = ev + __shfl_down_sync(FULLMASK, ev, 1);
            tv += __shfl_down_sync(FULLMASK, tv, 2);
            if (emit) {
                int idx = (k - 1) * OW + lofs;
                ou[idx] = tu * (1.0f/16.0f);
                ov[idx] = tv * (1.0f/16.0f);
            }
        }
        sPu = su;
        sPv = sv;
    }
}

__global__ __launch_bounds__(256, 6)
void roi_align_kernel(const float* __restrict__ feat, float* __restrict__ out) {
    __shared__ RW srw[PH];

    int n  = g_perm[blockIdx.x];
    int cg = blockIdx.y;          // 0..15, 16 channels per block
    int tid = threadIdx.x;
    int wid = tid >> 5, lane = tid & 31;

    if (tid < 2 * PH) {
        ((int4*)srw)[tid] = ((const int4*)g_rw[n])[tid];
    }
    __syncthreads();

    int4 hdr = g_hdr[n];
    int x0e = hdr.x, nw2 = hdr.y, boff = hdr.z, xs2 = hdr.w;
    int rows = g_rows[n];

    XEnt xe = g_x[n][lane];
    int c0 = xe.jlo & 1;
    int c1 = xe.jhi & 1;
    int je = c0 ? xe.jhi : xe.jlo;   // the even-column tap
    int jo = c0 ? xe.jlo : xe.jhi;   // the odd-column tap
    int le = (je >> 1) & 31, ew = je >> 6;
    int lo_ = (jo >> 1) & 31, ow = jo >> 6;
    float wx0 = xe.w0, wx1 = xe.w1;

    int c = cg * 16 + wid * 2;       // each warp: one channel pair
    const float* pu = feat + boff + x0e + c * HW_;
    const float* pv = pu + HW_;
    float* ou = out + (size_t)(n * C_ + c) * (OH * OW);
    float* ov = ou + OH * OW;

    if (nw2 == 1) {
        if (rows == 2)
            pair_proc<1,2>(pu, pv, srw, lane, xs2, c0, c1, le, lo_, ew, ow, wx0, wx1, ou, ov);
        else if (rows == 3)
            pair_proc<1,3>(pu, pv, srw, lane, xs2, c0, c1, le, lo_, ew, ow, wx0, wx1, ou, ov);
        else
            pair_proc<1,4>(pu, pv, srw, lane, xs2, c0, c1, le, lo_, ew, ow, wx0, wx1, ou, ov);
    } else {
        if (rows == 2)
            pair_proc<2,2>(pu, pv, srw, lane, xs2, c0, c1, le, lo_, ew, ow, wx0, wx1, ou, ov);
        else if (rows == 3)
            pair_proc<2,3>(pu, pv, srw, lane, xs2, c0, c1, le, lo_, ew, ow, wx0, wx1, ou, ov);
        else
            pair_proc<2,4>(pu, pv, srw, lane, xs2, c0, c1, le, lo_, ew, ow, wx0, wx1, ou, ov);
    }
}

extern "C" void kernel_launch(void* const* d_in, const int* in_sizes, int n_in,
                              void* d_out, int out_size) {
    const float* feat = (const float*)d_in[0];
    const float* rois = (const float*)d_in[1];
    float* out = (float*)d_out;

    roi_tab_kernel<<<NROI, 64>>>(rois);
    roi_sort_kernel<<<1, NROI>>>();
    dim3 grid(NROI, 16);
    roi_align_kernel<<<grid, 256>>>(feat, out);
}